// round 1
// baseline (speedup 1.0000x reference)
#include <cuda_runtime.h>
#include <cstdint>

#define C 128
#define HH 320
#define WW 320
#define BB 2
#define SEG 80
#define NBLK (BB*HH*(WW/SEG))   // 2560

// ---------------- device scratch (precomputed folded weights) ----------------
__device__ float g_WHt[C*C];                    // [k][m] = sum_i fuse[m,i]*h_pw[i,k]
__device__ float g_WVt[C*C];                    // [k][m] = sum_i fuse[m,128+i]*v_pw[i,k]
__device__ unsigned long long g_dm1t2[C*32];    // [m][j] splat2(w_dm1[j,m])
__device__ unsigned long long g_dm2s2[C*32];    // [c][j] splat2(w_dm2[c,j])

// ---------------- f32x2 helpers ----------------
__device__ __forceinline__ unsigned long long splat2(float w) {
    unsigned long long r; unsigned u = __float_as_uint(w);
    asm("mov.b64 %0, {%1, %1};" : "=l"(r) : "r"(u));
    return r;
}
__device__ __forceinline__ unsigned long long pack2(float a, float b) {
    unsigned long long r;
    asm("mov.b64 %0, {%1, %2};" : "=l"(r) : "r"(__float_as_uint(a)), "r"(__float_as_uint(b)));
    return r;
}
__device__ __forceinline__ void unpack2(unsigned long long v, float& a, float& b) {
    unsigned x, y; asm("mov.b64 {%0, %1}, %2;" : "=r"(x), "=r"(y) : "l"(v));
    a = __uint_as_float(x); b = __uint_as_float(y);
}
__device__ __forceinline__ unsigned long long ffma2(unsigned long long a, unsigned long long b, unsigned long long c) {
    unsigned long long d;
    asm("fma.rn.f32x2 %0, %1, %2, %3;" : "=l"(d) : "l"(a), "l"(b), "l"(c));
    return d;
}
__device__ __forceinline__ float lrelu(float v) { return v > 0.f ? v : 0.1f * v; }

// ---------------- kernel 0: fold weights ----------------
// W_H[m,k] = sum_c fuse[m,c]*h_pw[c,k];  W_V[m,k] = sum_c fuse[m,128+c]*v_pw[c,k]
// stored k-major: g_WHt[k*128+m]. Also splat-pack dm1 (transposed) and dm2.
#define SMEM_K0 ((129*128*2 + 256) * 4)
__global__ void __launch_bounds__(256) k_fold(
    const float* __restrict__ wf,   // [128][256]
    const float* __restrict__ pwh,  // [128][128]
    const float* __restrict__ pwv,  // [128][128]
    const float* __restrict__ dm1,  // [32][128]
    const float* __restrict__ dm2)  // [128][32]
{
    extern __shared__ float sm0[];
    float* wfH  = sm0;                 // [m][c] stride 129
    float* wfV  = sm0 + 129*128;
    float* colH = wfV + 129*128;       // [c]
    float* colV = colH + 128;
    const int k = blockIdx.x;
    const int tid = threadIdx.x;

    for (int i = tid; i < 128*128; i += 256) {
        int m = i >> 7, c = i & 127;
        wfH[m*129 + c] = wf[m*256 + c];
        wfV[m*129 + c] = wf[m*256 + 128 + c];
    }
    if (tid < 128) { colH[tid] = pwh[tid*128 + k]; colV[tid] = pwv[tid*128 + k]; }
    __syncthreads();

    {
        int m = tid & 127;
        bool isV = tid >= 128;
        const float* wrow = (isV ? wfV : wfH) + m*129;
        const float* col  = isV ? colV : colH;
        float acc = 0.f;
        #pragma unroll 8
        for (int c = 0; c < 128; ++c) acc = fmaf(wrow[c], col[c], acc);
        (isV ? g_WVt : g_WHt)[k*128 + m] = acc;
    }
    if (tid < 32) {
        g_dm1t2[k*32 + tid] = splat2(dm1[tid*128 + k]);
        g_dm2s2[k*32 + tid] = splat2(dm2[k*32 + tid]);
    }
}

// ---------------- main fused kernel ----------------
// grid: 2560 blocks = 640 rows x 4 col-segments of 80. 256 threads.
// smem layout (floats):
//   whsm [0,16384) wvsm [16384,32768)  Th [32768,43008) Tv [43008,53248)
//   dwhs [53248,53888) dwvs [53888,54528)
// overlays after GEMM: dm1s2/dm2s2 over whsm/wvsm (u64), Esm/Usm over Th/Tv.
#define SMEM_MAIN (54528 * 4)

__global__ void __launch_bounds__(256, 1) k_main(
    const float* __restrict__ x,
    const float* __restrict__ dwh,      // [128][5]
    const float* __restrict__ dwv,      // [128][5]
    const float* __restrict__ scale_p,
    float* __restrict__ out)
{
    extern __shared__ float sm[];
    float* whsm = sm;
    float* wvsm = sm + 16384;
    float* Th   = sm + 32768;
    float* Tv   = sm + 43008;
    float* dwhs = sm + 53248;
    float* dwvs = sm + 53888;
    // overlays
    unsigned long long* dm1s2 = (unsigned long long*)sm;            // 4096 u64
    unsigned long long* dm2s2 = (unsigned long long*)sm + 4096;     // 4096 u64
    float* Esm = sm + 32768;          // [p][m] stride 132 -> 10560 floats
    float* Usm = sm + 32768 + 10560;  // [p][j] stride 33  -> 2640 floats

    const int tid  = threadIdx.x;
    const int bx   = blockIdx.x;
    const int seg  = bx & 3;
    const int row  = bx >> 2;
    const int b    = row / HH;
    const int y    = row - b * HH;
    const int ai   = y % 5;
    const int y0   = y - ai;
    const int x0   = seg * SEG;

    // ---- preload folded weights + dw weights ----
    for (int i = tid; i < (C*C)/4; i += 256) {
        ((float4*)whsm)[i] = ((const float4*)g_WHt)[i];
        ((float4*)wvsm)[i] = ((const float4*)g_WVt)[i];
    }
    for (int i = tid; i < 640; i += 256) { dwhs[i] = dwh[i]; dwvs[i] = dwv[i]; }

    // ---- stage 1: depthwise convs + lrelu -> Th/Tv [128][80] ----
    const float* xb = x + (size_t)b * C * HH * WW;
    #pragma unroll 2
    for (int it = 0; it < 40; ++it) {
        int i = tid + 256 * it;
        int k = i / SEG;
        int p = i - k * SEG;
        int aj = p % 5;
        const float* xp = xb + ((size_t)k * HH + y0) * WW + x0 + p;   // 5 rows of block
        const float* xr = xb + ((size_t)k * HH + y)  * WW + x0 + p;   // this row
        float v0 = xp[0], v1 = xp[WW], v2 = xp[2*WW], v3 = xp[3*WW], v4 = xp[4*WW];
        // vertical depthwise (weight index q = r - ai + 2)
        float tv = 0.f;
        #pragma unroll
        for (int r = 0; r < 5; ++r) {
            int q = r - ai + 2;
            float vr = (r == 0) ? v0 : (r == 1) ? v1 : (r == 2) ? v2 : (r == 3) ? v3 : v4;
            if ((unsigned)q < 5u) tv = fmaf(dwvs[k*5 + q], vr, tv);
        }
        // horizontal depthwise: taps t, sample at column offset t-2 (within 5-block)
        float vai = (ai == 0) ? v0 : (ai == 1) ? v1 : (ai == 2) ? v2 : (ai == 3) ? v3 : v4;
        float th = dwhs[k*5 + 2] * vai;
        if (aj >= 2) th = fmaf(dwhs[k*5 + 0], xr[-2], th);
        if (aj >= 1) th = fmaf(dwhs[k*5 + 1], xr[-1], th);
        if (aj <= 3) th = fmaf(dwhs[k*5 + 3], xr[ 1], th);
        if (aj <= 2) th = fmaf(dwhs[k*5 + 4], xr[ 2], th);

        Th[k*SEG + p] = lrelu(th);
        Tv[k*SEG + p] = lrelu(tv);
    }
    __syncthreads();

    // ---- GEMM: epi[128][80] = W_H @ Th + W_V @ Tv, FFMA2 over pixel pairs ----
    const int lane = tid & 31;
    const int warp = tid >> 5;
    const int m0 = lane * 4;     // 4 output channels per thread
    const int p0 = warp * 10;    // 10 pixels (5 pairs) per warp
    unsigned long long acc[4][5];
    #pragma unroll
    for (int i = 0; i < 4; ++i)
        #pragma unroll
        for (int j = 0; j < 5; ++j) acc[i][j] = 0ull;

    #pragma unroll 2
    for (int k = 0; k < C; ++k) {
        float4 wh = *(const float4*)(whsm + k*C + m0);
        float4 wv = *(const float4*)(wvsm + k*C + m0);
        unsigned long long th[5], tv[5];
        #pragma unroll
        for (int j = 0; j < 5; ++j) {
            th[j] = *(const unsigned long long*)(Th + k*SEG + p0 + 2*j);
            tv[j] = *(const unsigned long long*)(Tv + k*SEG + p0 + 2*j);
        }
        unsigned long long wh2[4] = { splat2(wh.x), splat2(wh.y), splat2(wh.z), splat2(wh.w) };
        unsigned long long wv2[4] = { splat2(wv.x), splat2(wv.y), splat2(wv.z), splat2(wv.w) };
        #pragma unroll
        for (int i = 0; i < 4; ++i)
            #pragma unroll
            for (int j = 0; j < 5; ++j) {
                acc[i][j] = ffma2(wh2[i], th[j], acc[i][j]);
                acc[i][j] = ffma2(wv2[i], tv[j], acc[i][j]);
            }
    }
    __syncthreads();   // done reading Th/Tv and weight smem

    // ---- write epi tile to smem [p][m] (stride 132), load depth-MLP weights ----
    #pragma unroll
    for (int j = 0; j < 5; ++j) {
        float l0,h0,l1,h1,l2,h2,l3,h3;
        unpack2(acc[0][j], l0, h0); unpack2(acc[1][j], l1, h1);
        unpack2(acc[2][j], l2, h2); unpack2(acc[3][j], l3, h3);
        float4 vlo = { l0, l1, l2, l3 };
        float4 vhi = { h0, h1, h2, h3 };
        *(float4*)(Esm + (p0 + 2*j    ) * 132 + m0) = vlo;
        *(float4*)(Esm + (p0 + 2*j + 1) * 132 + m0) = vhi;
    }
    for (int i = tid; i < C*32; i += 256) {
        dm1s2[i] = g_dm1t2[i];
        dm2s2[i] = g_dm2s2[i];
    }
    __syncthreads();

    // ---- u = lrelu(dm1 @ epi): lane = j (0..31), each warp its own 10 pixels ----
    #pragma unroll
    for (int s = 0; s < 5; ++s) {
        int p = p0 + 2*s;
        const float* ea = Esm + p * 132;
        const float* eb = ea + 132;
        unsigned long long ua = 0ull, ub = 0ull;
        #pragma unroll 4
        for (int m = 0; m < 128; m += 2) {
            ua = ffma2(dm1s2[(m    )*32 + lane], pack2(ea[m    ], eb[m    ]), ua);
            ub = ffma2(dm1s2[(m + 1)*32 + lane], pack2(ea[m + 1], eb[m + 1]), ub);
        }
        float a0, a1, b0, b1;
        unpack2(ua, a0, a1); unpack2(ub, b0, b1);
        Usm[p*33 + lane]       = lrelu(a0 + b0);
        Usm[(p + 1)*33 + lane] = lrelu(a1 + b1);
    }
    __syncthreads();

    // ---- depth gate + residual output ----
    const float scl = scale_p[0];
    #pragma unroll 2
    for (int it = 0; it < 20; ++it) {
        int i = tid + 256 * it;           // i in [0, 128*40)
        int c  = i / 40;
        int p2 = i - c * 40;
        int p  = 2 * p2;
        const float* u0 = Usm + p * 33;
        const float* u1 = u0 + 33;
        unsigned long long sa = 0ull, sb = 0ull;
        #pragma unroll
        for (int j = 0; j < 32; j += 2) {
            sa = ffma2(dm2s2[c*32 + j    ], pack2(u0[j    ], u1[j    ]), sa);
            sb = ffma2(dm2s2[c*32 + j + 1], pack2(u0[j + 1], u1[j + 1]), sb);
        }
        float a0, a1, b0, b1;
        unpack2(sa, a0, a1); unpack2(sb, b0, b1);
        float s0 = a0 + b0, s1 = a1 + b1;
        float d0 = __frcp_rn(1.f + __expf(-s0));
        float d1 = __frcp_rn(1.f + __expf(-s1));
        float e0 = Esm[p*132 + c];
        float e1 = Esm[(p + 1)*132 + c];
        size_t gi = ((size_t)(b*C + c) * HH + y) * WW + x0 + p;
        float2 xv = *(const float2*)(x + gi);
        float2 o;
        o.x = fmaf(scl * d0, e0, xv.x);
        o.y = fmaf(scl * d1, e1, xv.y);
        *(float2*)(out + gi) = o;
    }
}

// ---------------- launch ----------------
extern "C" void kernel_launch(void* const* d_in, const int* in_sizes, int n_in,
                              void* d_out, int out_size) {
    (void)in_sizes; (void)n_in; (void)out_size;
    const float* x      = (const float*)d_in[0];
    const float* w_h_dw = (const float*)d_in[1];
    const float* w_h_pw = (const float*)d_in[2];
    const float* w_v_dw = (const float*)d_in[3];
    const float* w_v_pw = (const float*)d_in[4];
    const float* w_dm1  = (const float*)d_in[5];
    const float* w_dm2  = (const float*)d_in[6];
    const float* w_fuse = (const float*)d_in[7];
    const float* scale  = (const float*)d_in[8];
    float* out = (float*)d_out;

    cudaFuncSetAttribute(k_fold, cudaFuncAttributeMaxDynamicSharedMemorySize, SMEM_K0);
    cudaFuncSetAttribute(k_main, cudaFuncAttributeMaxDynamicSharedMemorySize, SMEM_MAIN);

    k_fold<<<128, 256, SMEM_K0>>>(w_fuse, w_h_pw, w_v_pw, w_dm1, w_dm2);
    k_main<<<NBLK, 256, SMEM_MAIN>>>(x, w_h_dw, w_v_dw, scale, out);
}

// round 2
// speedup vs baseline: 1.7971x; 1.7971x over previous
#include <cuda_runtime.h>
#include <cstdint>

#define C 128
#define HH 320
#define WW 320
#define BB 2
#define SEG 80
#define NBLK (BB*HH*(WW/SEG))   // 2560
#define NTH 320
#define MR 160                  // 128 epi rows + 32 folded-dm1 rows

typedef unsigned long long u64;

// ---------------- device scratch (precomputed folded weights) ----------------
__device__ float g_WHc[C*MR];     // [k][r]: r<128 -> W_H[r][k], r>=128 -> D_H[r-128][k]
__device__ float g_WVc[C*MR];
__device__ float g_FH[32*C];      // dm1 @ fuse_H
__device__ float g_FV[32*C];      // dm1 @ fuse_V
__device__ float g_dm2t[32*C];    // [j][c] = dm2[c][j]

// ---------------- f32x2 helpers ----------------
__device__ __forceinline__ u64 splat2(float w) {
    u64 r; unsigned u = __float_as_uint(w);
    asm("mov.b64 %0, {%1, %1};" : "=l"(r) : "r"(u));
    return r;
}
__device__ __forceinline__ u64 pack2(float a, float b) {
    u64 r;
    asm("mov.b64 %0, {%1, %2};" : "=l"(r) : "r"(__float_as_uint(a)), "r"(__float_as_uint(b)));
    return r;
}
__device__ __forceinline__ void unpack2(u64 v, float& a, float& b) {
    unsigned x, y; asm("mov.b64 {%0, %1}, %2;" : "=r"(x), "=r"(y) : "l"(v));
    a = __uint_as_float(x); b = __uint_as_float(y);
}
__device__ __forceinline__ u64 ffma2(u64 a, u64 b, u64 c) {
    u64 d;
    asm("fma.rn.f32x2 %0, %1, %2, %3;" : "=l"(d) : "l"(a), "l"(b), "l"(c));
    return d;
}
__device__ __forceinline__ float lrelu(float v) { return v > 0.f ? v : 0.1f * v; }

// ---------------- fold 1: FH/FV = dm1 @ fuse_{H,V}; transpose dm2 ----------------
__global__ void __launch_bounds__(128) k_fold1(
    const float* __restrict__ wf,   // [128][256]
    const float* __restrict__ dm1,  // [32][128]
    const float* __restrict__ dm2)  // [128][32]
{
    __shared__ float drow[128];
    const int j  = blockIdx.x & 31;
    const int br = blockIdx.x >> 5;
    const int c  = threadIdx.x;
    drow[c] = dm1[j*128 + c];
    __syncthreads();
    float acc = 0.f;
    const float* fcol = wf + br*128 + c;
    #pragma unroll 8
    for (int m = 0; m < 128; ++m) acc = fmaf(drow[m], __ldg(fcol + m*256), acc);
    (br ? g_FV : g_FH)[j*128 + c] = acc;
    if (blockIdx.x == 0) {
        #pragma unroll
        for (int jj = 0; jj < 32; ++jj) g_dm2t[jj*128 + c] = dm2[c*32 + jj];
    }
}

// ---------------- fold 2: combined weights, column k ----------------
// g_WHc[k][r] = dot(rowH[r][:], pwh[:,k]),  rowH = [fuse_H ; FH]   (160 rows)
#define SMEM_F2 ((160*129*2 + 256) * 4)
__global__ void __launch_bounds__(NTH) k_fold2(
    const float* __restrict__ wf,   // [128][256]
    const float* __restrict__ pwh,  // [128][128]
    const float* __restrict__ pwv)  // [128][128]
{
    extern __shared__ float s[];
    float* RH = s;                  // [160][129]
    float* RV = s + 160*129;
    float* cH = RV + 160*129;       // [128]
    float* cV = cH + 128;
    const int k = blockIdx.x;
    const int t = threadIdx.x;

    for (int i = t; i < 160*128; i += NTH) {
        int r = i >> 7, c = i & 127;
        RH[r*129 + c] = (r < 128) ? wf[r*256 + c]       : g_FH[(r-128)*128 + c];
        RV[r*129 + c] = (r < 128) ? wf[r*256 + 128 + c] : g_FV[(r-128)*128 + c];
    }
    if (t < 128) { cH[t] = pwh[t*128 + k]; cV[t] = pwv[t*128 + k]; }
    __syncthreads();

    const int r  = t % 160;
    const int br = t / 160;
    const float* row = (br ? RV : RH) + r*129;
    const float* col = br ? cV : cH;
    float acc = 0.f;
    #pragma unroll 8
    for (int c = 0; c < 128; ++c) acc = fmaf(row[c], col[c], acc);
    (br ? g_WVc : g_WHc)[k*MR + r] = acc;
}

// ---------------- main fused kernel ----------------
// grid 2560 = 640 rows x 4 col-segments of 80; 320 threads; 2 CTAs/SM.
// smem (floats): Th[0,10240) Tv[10240,20480) dwhs[20480,21120) dwvs[21120,21760)
// overlays after GEMM (over Th/Tv): Esm [80][132] at 0; Usm [32][88] at 10560.
#define SMEM_MAIN (21760 * 4)

__global__ void __launch_bounds__(NTH, 2) k_main(
    const float* __restrict__ x,
    const float* __restrict__ dwh,      // [128][5]
    const float* __restrict__ dwv,      // [128][5]
    const float* __restrict__ scale_p,
    float* __restrict__ out)
{
    extern __shared__ float sm[];
    float* Th   = sm;
    float* Tv   = sm + 10240;
    float* dwhs = sm + 20480;
    float* dwvs = sm + 21120;
    float* Esm  = sm;             // [p][m] stride 132 (10560 fl)
    float* Usm  = sm + 10560;     // [j][p] stride 88  (2816 fl)

    const int tid = threadIdx.x;
    const int bx  = blockIdx.x;
    const int seg = bx & 3;
    const int row = bx >> 2;
    const int b   = row / HH;
    const int y   = row - b * HH;
    const int ai  = y % 5;
    const int y0  = y - ai;
    const int x0  = seg * SEG;

    // ---- load depthwise weights ----
    for (int i = tid; i < 640; i += NTH) { dwhs[i] = dwh[i]; dwvs[i] = dwv[i]; }
    __syncthreads();

    // ---- stage 1: depthwise convs + lrelu -> Th/Tv [128][80] ----
    const float* xb = x + (size_t)b * C * HH * WW;
    #pragma unroll 2
    for (int it = 0; it < 32; ++it) {
        int i = tid + NTH * it;
        int k = i / SEG;
        int p = i - k * SEG;
        int aj = p % 5;
        const float* xp = xb + ((size_t)k * HH + y0) * WW + x0 + p;
        const float* xr = xb + ((size_t)k * HH + y)  * WW + x0 + p;
        float v0 = xp[0], v1 = xp[WW], v2 = xp[2*WW], v3 = xp[3*WW], v4 = xp[4*WW];
        float tv = 0.f;
        #pragma unroll
        for (int r = 0; r < 5; ++r) {
            int q = r - ai + 2;
            float vr = (r == 0) ? v0 : (r == 1) ? v1 : (r == 2) ? v2 : (r == 3) ? v3 : v4;
            if ((unsigned)q < 5u) tv = fmaf(dwvs[k*5 + q], vr, tv);
        }
        float vai = (ai == 0) ? v0 : (ai == 1) ? v1 : (ai == 2) ? v2 : (ai == 3) ? v3 : v4;
        float th = dwhs[k*5 + 2] * vai;
        if (aj >= 2) th = fmaf(dwhs[k*5 + 0], xr[-2], th);
        if (aj >= 1) th = fmaf(dwhs[k*5 + 1], xr[-1], th);
        if (aj <= 3) th = fmaf(dwhs[k*5 + 3], xr[ 1], th);
        if (aj <= 2) th = fmaf(dwhs[k*5 + 4], xr[ 2], th);
        Th[k*SEG + p] = lrelu(th);
        Tv[k*SEG + p] = lrelu(tv);
    }
    __syncthreads();

    // ---- GEMM: [epi;u_pre][160][80] = Wc_H @ Th + Wc_V @ Tv ----
    const int mg = tid % 40;      // 40 row-groups of 4
    const int pg = tid / 40;      // 8 pixel-groups of 10
    const int m0 = mg * 4;
    const int p0 = pg * 10;
    u64 acc[4][5];
    #pragma unroll
    for (int i = 0; i < 4; ++i)
        #pragma unroll
        for (int j = 0; j < 5; ++j) acc[i][j] = 0ull;

    #pragma unroll 2
    for (int k = 0; k < C; ++k) {
        float4 wh = __ldg((const float4*)(g_WHc + k*MR + m0));
        float4 wv = __ldg((const float4*)(g_WVc + k*MR + m0));
        u64 th[5], tv[5];
        #pragma unroll
        for (int j = 0; j < 5; ++j) {
            th[j] = *(const u64*)(Th + k*SEG + p0 + 2*j);
            tv[j] = *(const u64*)(Tv + k*SEG + p0 + 2*j);
        }
        u64 wh2[4] = { splat2(wh.x), splat2(wh.y), splat2(wh.z), splat2(wh.w) };
        u64 wv2[4] = { splat2(wv.x), splat2(wv.y), splat2(wv.z), splat2(wv.w) };
        #pragma unroll
        for (int i = 0; i < 4; ++i)
            #pragma unroll
            for (int j = 0; j < 5; ++j) {
                acc[i][j] = ffma2(wh2[i], th[j], acc[i][j]);
                acc[i][j] = ffma2(wv2[i], tv[j], acc[i][j]);
            }
    }
    __syncthreads();   // done reading Th/Tv

    // ---- scatter results: epi rows -> Esm [p][m], u rows -> lrelu -> Usm [j][p] ----
    if (mg < 32) {
        #pragma unroll
        for (int j = 0; j < 5; ++j) {
            float l0,h0,l1,h1,l2,h2,l3,h3;
            unpack2(acc[0][j], l0, h0); unpack2(acc[1][j], l1, h1);
            unpack2(acc[2][j], l2, h2); unpack2(acc[3][j], l3, h3);
            float4 vlo = { l0, l1, l2, l3 };
            float4 vhi = { h0, h1, h2, h3 };
            *(float4*)(Esm + (p0 + 2*j    ) * 132 + m0) = vlo;
            *(float4*)(Esm + (p0 + 2*j + 1) * 132 + m0) = vhi;
        }
    } else {
        int j0 = (mg - 32) * 4;
        #pragma unroll
        for (int s = 0; s < 5; ++s) {
            #pragma unroll
            for (int i = 0; i < 4; ++i) {
                float a, b2;
                unpack2(acc[i][s], a, b2);
                *(u64*)(Usm + (j0 + i)*88 + p0 + 2*s) = pack2(lrelu(a), lrelu(b2));
            }
        }
    }
    __syncthreads();

    // ---- dm2 @ u -> sigmoid gate; out = x + scl * epi * gate ----
    const int cg = tid / 10;      // 32 groups of 4 channels
    const int pq = tid % 10;      // 10 groups of 8 pixels
    const int c0 = cg * 4;
    const int q0 = pq * 8;
    u64 a2[4][4];
    #pragma unroll
    for (int i = 0; i < 4; ++i)
        #pragma unroll
        for (int s = 0; s < 4; ++s) a2[i][s] = 0ull;

    #pragma unroll 4
    for (int j = 0; j < 32; ++j) {
        float4 w = __ldg((const float4*)(g_dm2t + j*128 + c0));
        u64 w2[4] = { splat2(w.x), splat2(w.y), splat2(w.z), splat2(w.w) };
        u64 up[4];
        #pragma unroll
        for (int s = 0; s < 4; ++s) up[s] = *(const u64*)(Usm + j*88 + q0 + 2*s);
        #pragma unroll
        for (int i = 0; i < 4; ++i)
            #pragma unroll
            for (int s = 0; s < 4; ++s) a2[i][s] = ffma2(w2[i], up[s], a2[i][s]);
    }

    const float scl = scale_p[0];
    #pragma unroll
    for (int i = 0; i < 4; ++i) {
        int c = c0 + i;
        size_t base = ((size_t)(b*C + c) * HH + y) * WW + x0 + q0;
        #pragma unroll
        for (int s = 0; s < 4; ++s) {
            float s0, s1;
            unpack2(a2[i][s], s0, s1);
            float d0 = __frcp_rn(1.f + __expf(-s0));
            float d1 = __frcp_rn(1.f + __expf(-s1));
            float e0 = Esm[(q0 + 2*s    ) * 132 + c];
            float e1 = Esm[(q0 + 2*s + 1) * 132 + c];
            float2 xv = *(const float2*)(x + base + 2*s);
            float2 o;
            o.x = fmaf(scl * d0, e0, xv.x);
            o.y = fmaf(scl * d1, e1, xv.y);
            *(float2*)(out + base + 2*s) = o;
        }
    }
}

// ---------------- launch ----------------
extern "C" void kernel_launch(void* const* d_in, const int* in_sizes, int n_in,
                              void* d_out, int out_size) {
    (void)in_sizes; (void)n_in; (void)out_size;
    const float* x      = (const float*)d_in[0];
    const float* w_h_dw = (const float*)d_in[1];
    const float* w_h_pw = (const float*)d_in[2];
    const float* w_v_dw = (const float*)d_in[3];
    const float* w_v_pw = (const float*)d_in[4];
    const float* w_dm1  = (const float*)d_in[5];
    const float* w_dm2  = (const float*)d_in[6];
    const float* w_fuse = (const float*)d_in[7];
    const float* scale  = (const float*)d_in[8];
    float* out = (float*)d_out;

    cudaFuncSetAttribute(k_fold2, cudaFuncAttributeMaxDynamicSharedMemorySize, SMEM_F2);
    cudaFuncSetAttribute(k_main,  cudaFuncAttributeMaxDynamicSharedMemorySize, SMEM_MAIN);

    k_fold1<<<64, 128>>>(w_fuse, w_dm1, w_dm2);
    k_fold2<<<128, NTH, SMEM_F2>>>(w_fuse, w_h_pw, w_v_pw);
    k_main<<<NBLK, NTH, SMEM_MAIN>>>(x, w_h_dw, w_v_dw, scale, out);
}